// round 13
// baseline (speedup 1.0000x reference)
#include <cuda_runtime.h>
#include <cuda_bf16.h>
#include <math.h>
#include <stdint.h>

#define NQ 16384
#define NC 8192
#define DD 256
#define ZELEMS 4194304
#define LOSS_OFF 4194304
#define PERP_OFF 4194305
#define UNIQ_OFF 4194306
#define IDX_OFF  4194307

// ---------------- device scratch ----------------
__device__ float          g_cnorm[NC];
__device__ int            g_counts[NC];
__device__ int            g_idx[NQ];
__device__ float          g_lpart[16384];
__device__ __nv_bfloat16  g_wB[NC * DD];          // bf16 codebook [code][k], swizzle-ready rows
__device__ unsigned char  g_zB[128 * 65536];      // pre-swizzled bf16 A tile per qslab
__device__ float          g_zT[NQ * DD];          // channel-last queries (rescore)
__device__ float          g_bm8[1024 * NQ];       // per-8-code bin minima, bin-major

// ---------------- PTX helpers ----------------
__device__ __forceinline__ uint32_t s2u(const void* p) {
    uint32_t a;
    asm("{ .reg .u64 t; cvta.to.shared.u64 t, %1; cvt.u32.u64 %0, t; }" : "=r"(a) : "l"(p));
    return a;
}
__device__ __forceinline__ void ldsm4(uint32_t addr, uint32_t& r0, uint32_t& r1,
                                      uint32_t& r2, uint32_t& r3) {
    asm volatile("ldmatrix.sync.aligned.m8n8.x4.shared.b16 {%0,%1,%2,%3}, [%4];"
                 : "=r"(r0), "=r"(r1), "=r"(r2), "=r"(r3) : "r"(addr));
}
__device__ __forceinline__ void mma16816(float* d, const uint32_t* a, uint32_t b0, uint32_t b1) {
    asm volatile(
        "mma.sync.aligned.m16n8k16.row.col.f32.bf16.bf16.f32 "
        "{%0,%1,%2,%3},{%4,%5,%6,%7},{%8,%9},{%0,%1,%2,%3};"
        : "+f"(d[0]), "+f"(d[1]), "+f"(d[2]), "+f"(d[3])
        : "r"(a[0]), "r"(a[1]), "r"(a[2]), "r"(a[3]), "r"(b0), "r"(b1));
}
#define CPASYNC(dst, src) \
    asm volatile("cp.async.cg.shared.global [%0], [%1], 16;" :: "r"(dst), "l"(src))
#define CPCOMMIT() asm volatile("cp.async.commit_group;")
#define CPWAIT(n)  asm volatile("cp.async.wait_group %0;" :: "n"(n))

// smem: A 64K | B0 64K | B1 64K | cn 32K
#define SM_A  0
#define SM_B0 65536
#define SM_B1 131072
#define SM_CN 196608
#define SMEM_SZ 229376

// ---------------- prep ----------------
__global__ void k_zero() {
    int t = blockIdx.x * blockDim.x + threadIdx.x;
    if (t < NC) g_counts[t] = 0;
}

__global__ void k_cnorm(const float* __restrict__ w) {
    int warp = threadIdx.x >> 5, lane = threadIdx.x & 31;
    int c = blockIdx.x * 8 + warp;
    const float* row = w + c * DD;
    float s = 0.f;
#pragma unroll
    for (int j = 0; j < 8; j++) { float v = row[lane + j * 32]; s += v * v; }
#pragma unroll
    for (int off = 16; off; off >>= 1) s += __shfl_xor_sync(0xffffffffu, s, off);
    if (lane == 0) g_cnorm[c] = s;
}

__global__ void k_wbf16(const float* __restrict__ w) {
    int t = blockIdx.x * 256 + threadIdx.x;
    g_wB[t] = __float2bfloat16(w[t]);
}

// fp32 channel-last copy for rescore
__global__ void k_zt(const float* __restrict__ z) {
    __shared__ float tile[32][33];
    int s0 = blockIdx.x * 32, c0 = blockIdx.y * 32, b = blockIdx.z;
    int tx = threadIdx.x, ty = threadIdx.y;
#pragma unroll
    for (int r = 0; r < 4; r++)
        tile[ty + r * 8][tx] = z[b * 1048576 + (c0 + ty + r * 8) * 4096 + s0 + tx];
    __syncthreads();
#pragma unroll
    for (int r = 0; r < 4; r++)
        g_zT[(b * 4096 + s0 + ty + r * 8) * DD + c0 + tx] = tile[tx][ty + r * 8];
}

// pre-swizzled bf16 A tiles: one 64KB image per 128-query slab
__global__ void k_zb(const float* __restrict__ z) {
    int qs = blockIdx.x;
    int b = qs >> 5, s0 = (qs & 31) * 128;
    const float* zb = z + b * 1048576 + s0;
    unsigned char* dst = g_zB + (size_t)qs * 65536;
    for (int e = threadIdx.x; e < 32768; e += 256) {
        int c = e >> 7, r = e & 127;
        float v = zb[c * 4096 + r];
        int off = r * 512 + ((((c >> 3) ^ (r & 7)) << 4)) + (c & 7) * 2;
        *(__nv_bfloat16*)(dst + off) = __float2bfloat16(v);
    }
}

// ---------------- HMMA filter: 512 threads, warp tile 32x32 ----------------
// grid 128 (one 128-query slab), loops 64 code tiles of 128.
__global__ void __launch_bounds__(512, 1) k_tc() {
    extern __shared__ char smem[];
    uint32_t sb = s2u(smem);
    float* cn_s = (float*)(smem + SM_CN);

    int tid = threadIdx.x, lane = tid & 31, wid = tid >> 5;
    int qs = blockIdx.x;
    int qbase = qs * 128;

    // A tile via cp.async (group 0)
    {
        const char* as = (const char*)g_zB + (size_t)qs * 65536;
#pragma unroll
        for (int i = 0; i < 8; i++) {
            int e = tid + i * 512;
            CPASYNC(sb + SM_A + e * 16, as + (size_t)e * 16);
        }
        CPCOMMIT();
    }
    // B tile 0 (group 1)
    {
        const char* gs = (const char*)g_wB;
#pragma unroll
        for (int i = 0; i < 8; i++) {
            int e = tid + i * 512;
            int n = e >> 5, kc = e & 31;
            CPASYNC(sb + SM_B0 + n * 512 + ((kc ^ (n & 7)) << 4), gs + n * 512 + kc * 16);
        }
        CPCOMMIT();
    }
    // cnorm -> smem
    {
        const float4* src = (const float4*)g_cnorm;
        float4* dstv = (float4*)cn_s;
        for (int i = tid; i < 2048; i += 512) dstv[i] = src[i];
    }

    int wm = (wid & 3) * 32, wn = (wid >> 2) * 32;
    int aRow = wm + (lane & 15);
    int aSw = lane & 7;
    int aKo = lane >> 4;
    int bN0 = wn + (lane & 7) + ((lane >> 4) << 3);
    int bKo = (lane >> 3) & 1;

    for (int t = 0; t < 64; t++) {
        if (t + 1 < 64) {
            const char* gs = (const char*)g_wB + (size_t)(t + 1) * 65536;
            uint32_t bb = sb + (((t + 1) & 1) ? SM_B1 : SM_B0);
#pragma unroll
            for (int i = 0; i < 8; i++) {
                int e = tid + i * 512;
                int n = e >> 5, kc = e & 31;
                CPASYNC(bb + n * 512 + ((kc ^ (n & 7)) << 4), gs + n * 512 + kc * 16);
            }
            CPCOMMIT();
            CPWAIT(1);          // current A(+prior B) and B(t) complete
        } else {
            CPWAIT(0);
        }
        __syncthreads();

        uint32_t sB = sb + ((t & 1) ? SM_B1 : SM_B0);
        float d[2][4][4];
#pragma unroll
        for (int mi = 0; mi < 2; mi++)
#pragma unroll
            for (int ni = 0; ni < 4; ni++)
#pragma unroll
                for (int u = 0; u < 4; u++) d[mi][ni][u] = 0.f;

#pragma unroll 4
        for (int ks = 0; ks < 16; ks++) {
            int kkA = 2 * ks + aKo;
            uint32_t a0[4], a1[4];
            ldsm4(sb + SM_A + aRow * 512 + ((kkA ^ aSw) << 4), a0[0], a0[1], a0[2], a0[3]);
            ldsm4(sb + SM_A + (aRow + 16) * 512 + ((kkA ^ aSw) << 4), a1[0], a1[1], a1[2], a1[3]);
            int kkB = 2 * ks + bKo;
#pragma unroll
            for (int nb = 0; nb < 2; nb++) {
                int n = bN0 + nb * 16;
                uint32_t b0, b1, b2, b3;
                ldsm4(sB + n * 512 + ((kkB ^ (lane & 7)) << 4), b0, b1, b2, b3);
                mma16816(d[0][nb * 2], a0, b0, b1);
                mma16816(d[0][nb * 2 + 1], a0, b2, b3);
                mma16816(d[1][nb * 2], a1, b0, b1);
                mma16816(d[1][nb * 2 + 1], a1, b2, b3);
            }
        }

        // epilogue: dist = cn - 2*dot; per-8-col bin min; lanes%4==0 write
#pragma unroll
        for (int mi = 0; mi < 2; mi++) {
#pragma unroll
            for (int ni = 0; ni < 4; ni++) {
                float2 cn2 = *(float2*)&cn_s[t * 128 + wn + ni * 8 + (lane & 3) * 2];
                float v0 = fminf(cn2.x - 2.f * d[mi][ni][0], cn2.y - 2.f * d[mi][ni][1]);
                float v1 = fminf(cn2.x - 2.f * d[mi][ni][2], cn2.y - 2.f * d[mi][ni][3]);
                v0 = fminf(v0, __shfl_xor_sync(0xffffffffu, v0, 1));
                v0 = fminf(v0, __shfl_xor_sync(0xffffffffu, v0, 2));
                v1 = fminf(v1, __shfl_xor_sync(0xffffffffu, v1, 1));
                v1 = fminf(v1, __shfl_xor_sync(0xffffffffu, v1, 2));
                if ((lane & 3) == 0) {
                    int bin = t * 16 + (wn >> 3) + ni;
                    int q0 = qbase + wm + mi * 16 + (lane >> 2);
                    g_bm8[(size_t)bin * NQ + q0] = v0;
                    g_bm8[(size_t)bin * NQ + q0 + 8] = v1;
                }
            }
        }
        __syncthreads();
    }
}

// ---------------- exact rescore of candidate bins (+ idx output) ----------------
__global__ void k_rescore(const float* __restrict__ w, float* __restrict__ out) {
    int q = blockIdx.x * 128 + threadIdx.x;
    float m = __int_as_float(0x7f800000);
#pragma unroll 8
    for (int i = 0; i < 1024; i++) m = fminf(m, g_bm8[(size_t)i * NQ + q]);
    float thr = m + 2.0f;                        // covers bf16 approx error

    float best = __int_as_float(0x7f800000);
    int bi = 0;
    const float4* zq4 = (const float4*)(g_zT + (size_t)q * DD);
    for (int i = 0; i < 1024; i++) {
        if (g_bm8[(size_t)i * NQ + q] <= thr) {
            float acc[8];
#pragma unroll
            for (int k = 0; k < 8; k++) acc[k] = 0.f;
            const float4* wr = (const float4*)(w + (size_t)i * 8 * DD);
            for (int c4 = 0; c4 < 64; c4++) {
                float4 zv = __ldg(&zq4[c4]);
#pragma unroll
                for (int k = 0; k < 8; k++) {
                    float4 wv = __ldg(&wr[k * 64 + c4]);
                    acc[k] = fmaf(zv.x, wv.x, acc[k]);
                    acc[k] = fmaf(zv.y, wv.y, acc[k]);
                    acc[k] = fmaf(zv.z, wv.z, acc[k]);
                    acc[k] = fmaf(zv.w, wv.w, acc[k]);
                }
            }
#pragma unroll
            for (int k = 0; k < 8; k++) {
                int c = i * 8 + k;
                float sc = g_cnorm[c] - 2.f * acc[k];
                if (sc < best) { best = sc; bi = c; }
            }
        }
    }
    g_idx[q] = bi;
    out[IDX_OFF + q] = (float)bi;
    atomicAdd(&g_counts[bi], 1);
}

// ---------------- gather + straight-through + loss partials ----------------
__global__ void k_gather(const float* __restrict__ z, const float* __restrict__ w,
                         float* __restrict__ out) {
    int o = blockIdx.x * 256 + threadIdx.x;
    int s = o & 4095;
    int c = (o >> 12) & 255;
    int b = o >> 20;
    int n = b * 4096 + s;
    int id = g_idx[n];
    float zv = z[o];
    float wv = __ldg(w + id * DD + c);
    float d = wv - zv;
    out[o] = zv + d;

    float v = d * d;
#pragma unroll
    for (int off = 16; off; off >>= 1) v += __shfl_xor_sync(0xffffffffu, v, off);
    __shared__ float red[8];
    if ((threadIdx.x & 31) == 0) red[threadIdx.x >> 5] = v;
    __syncthreads();
    if (threadIdx.x == 0) {
        float tsum = 0.f;
#pragma unroll
        for (int i = 0; i < 8; i++) tsum += red[i];
        g_lpart[blockIdx.x] = tsum;
    }
}

__global__ void k_final(float* __restrict__ out) {
    __shared__ double ds[32];
    __shared__ float es[32];
    __shared__ int us[32];
    int t = threadIdx.x, lane = t & 31, warp = t >> 5;

    double lsum = 0.0;
    for (int i = t; i < 16384; i += 1024) lsum += (double)g_lpart[i];

    float ent = 0.f; int uniq = 0;
    for (int c = t; c < NC; c += 1024) {
        int cnt = g_counts[c];
        float p = (float)cnt * (1.0f / 16384.0f);
        ent += p * logf(p + 1e-10f);
        uniq += (cnt > 0);
    }
#pragma unroll
    for (int off = 16; off; off >>= 1) {
        lsum += __shfl_xor_sync(0xffffffffu, lsum, off);
        ent += __shfl_xor_sync(0xffffffffu, ent, off);
        uniq += __shfl_xor_sync(0xffffffffu, uniq, off);
    }
    if (lane == 0) { ds[warp] = lsum; es[warp] = ent; us[warp] = uniq; }
    __syncthreads();
    if (t == 0) {
        double L = 0.0; float E = 0.f; int U = 0;
        for (int i = 0; i < 32; i++) { L += ds[i]; E += es[i]; U += us[i]; }
        out[LOSS_OFF] = 0.25f * (float)(L * (1.0 / 4194304.0));
        out[PERP_OFF] = expf(-E);
        out[UNIQ_OFF] = (float)U;
    }
}

// ---------------- launch ----------------
extern "C" void kernel_launch(void* const* d_in, const int* in_sizes, int n_in,
                              void* d_out, int out_size) {
    const float* z = (const float*)d_in[0];
    const float* w = (const float*)d_in[1];
    float* out = (float*)d_out;

    cudaFuncSetAttribute(k_tc, cudaFuncAttributeMaxDynamicSharedMemorySize, SMEM_SZ);

    k_zero<<<8, 1024>>>();
    k_cnorm<<<NC / 8, 256>>>(w);
    k_wbf16<<<NC, 256>>>(w);
    k_zt<<<dim3(128, 8, 4), dim3(32, 8)>>>(z);
    k_zb<<<128, 256>>>(z);
    k_tc<<<128, 512, SMEM_SZ>>>();
    k_rescore<<<NQ / 128, 128>>>(w, out);
    k_gather<<<ZELEMS / 256, 256>>>(z, w, out);
    k_final<<<1, 1024>>>(out);
}

// round 14
// speedup vs baseline: 1.4820x; 1.4820x over previous
#include <cuda_runtime.h>
#include <cuda_bf16.h>
#include <math.h>
#include <stdint.h>

#define NQ 16384
#define NC 8192
#define DD 256
#define ZELEMS 4194304
#define LOSS_OFF 4194304
#define PERP_OFF 4194305
#define UNIQ_OFF 4194306
#define IDX_OFF  4194307

// ---------------- device scratch ----------------
__device__ float          g_cnorm[NC];
__device__ int            g_counts[NC];
__device__ int            g_idx[NQ];
__device__ float          g_lpart[16384];
__device__ __nv_bfloat16  g_wB[NC * DD];          // bf16 codebook [code][k]
__device__ unsigned char  g_zB[128 * 65536];      // pre-swizzled bf16 A tile per qslab
__device__ float          g_zT[NQ * DD];          // channel-last queries (rescore)
__device__ float          g_bm8[1024 * NQ];       // per-8-code bin minima, bin-major

// ---------------- PTX helpers ----------------
__device__ __forceinline__ uint32_t s2u(const void* p) {
    uint32_t a;
    asm("{ .reg .u64 t; cvta.to.shared.u64 t, %1; cvt.u32.u64 %0, t; }" : "=r"(a) : "l"(p));
    return a;
}
__device__ __forceinline__ void ldsm4(uint32_t addr, uint32_t& r0, uint32_t& r1,
                                      uint32_t& r2, uint32_t& r3) {
    asm volatile("ldmatrix.sync.aligned.m8n8.x4.shared.b16 {%0,%1,%2,%3}, [%4];"
                 : "=r"(r0), "=r"(r1), "=r"(r2), "=r"(r3) : "r"(addr));
}
__device__ __forceinline__ void mma16816(float* d, const uint32_t* a, uint32_t b0, uint32_t b1) {
    asm volatile(
        "mma.sync.aligned.m16n8k16.row.col.f32.bf16.bf16.f32 "
        "{%0,%1,%2,%3},{%4,%5,%6,%7},{%8,%9},{%0,%1,%2,%3};"
        : "+f"(d[0]), "+f"(d[1]), "+f"(d[2]), "+f"(d[3])
        : "r"(a[0]), "r"(a[1]), "r"(a[2]), "r"(a[3]), "r"(b0), "r"(b1));
}
#define CPASYNC(dst, src) \
    asm volatile("cp.async.cg.shared.global [%0], [%1], 16;" :: "r"(dst), "l"(src))
#define CPCOMMIT() asm volatile("cp.async.commit_group;")
#define CPWAIT(n)  asm volatile("cp.async.wait_group %0;" :: "n"(n))

// smem: A 64K | B0 64K | B1 64K | cn 32K
#define SM_A  0
#define SM_B0 65536
#define SM_B1 131072
#define SM_CN 196608
#define SMEM_SZ 229376

// ---------------- fused w-prep: zero counts + cnorm + bf16 codebook ----------------
__global__ void k_prepw(const float* __restrict__ w) {
    int tid = threadIdx.x;
    if (blockIdx.x < 8) {
        for (int i = tid; i < 1024; i += 256) g_counts[blockIdx.x * 1024 + i] = 0;
    }
    int warp = tid >> 5, lane = tid & 31;
    int c = blockIdx.x * 8 + warp;
    const float* row = w + (size_t)c * DD;
    float s = 0.f;
#pragma unroll
    for (int j = 0; j < 8; j++) {
        float v = row[lane + j * 32];
        s += v * v;
        g_wB[(size_t)c * DD + lane + j * 32] = __float2bfloat16(v);
    }
#pragma unroll
    for (int off = 16; off; off >>= 1) s += __shfl_xor_sync(0xffffffffu, s, off);
    if (lane == 0) g_cnorm[c] = s;
}

// ---------------- fused z-prep: channel-last fp32 + pre-swizzled bf16 A tiles ----------
__global__ void k_z(const float* __restrict__ z) {
    __shared__ float tile[32][33];
    int s0 = blockIdx.x * 32, c0 = blockIdx.y * 32, b = blockIdx.z;
    int tx = threadIdx.x, ty = threadIdx.y;
#pragma unroll
    for (int r = 0; r < 4; r++)
        tile[ty + r * 8][tx] = z[b * 1048576 + (c0 + ty + r * 8) * 4096 + s0 + tx];
    __syncthreads();
    int qs = b * 32 + (s0 >> 7);
    unsigned char* zbdst = g_zB + (size_t)qs * 65536;
#pragma unroll
    for (int r = 0; r < 4; r++) {
        int s = s0 + ty + r * 8;
        int c = c0 + tx;
        float v = tile[tx][ty + r * 8];
        g_zT[(size_t)(b * 4096 + s) * DD + c] = v;
        int rr = s & 127;
        int off = rr * 512 + ((((c >> 3) ^ (rr & 7)) << 4)) + (c & 7) * 2;
        *(__nv_bfloat16*)(zbdst + off) = __float2bfloat16(v);
    }
}

// ---------------- HMMA filter + inline exact rescore ----------------
// grid 128 (one 128-query slab), 256 thr, 64 code tiles of 128.
__global__ void __launch_bounds__(256, 1) k_tc(const float* __restrict__ w,
                                               float* __restrict__ out) {
    extern __shared__ char smem[];
    uint32_t sb = s2u(smem);
    float* cn_s = (float*)(smem + SM_CN);

    int tid = threadIdx.x, lane = tid & 31, wid = tid >> 5;
    int qs = blockIdx.x;
    int qbase = qs * 128;

    // A tile via cp.async (group 0)
    {
        const char* as = (const char*)g_zB + (size_t)qs * 65536;
#pragma unroll
        for (int i = 0; i < 16; i++) {
            int e = tid + i * 256;
            CPASYNC(sb + SM_A + e * 16, as + (size_t)e * 16);
        }
        CPCOMMIT();
    }
    // B tile 0 (group 1)
    {
        const char* gs = (const char*)g_wB;
#pragma unroll
        for (int i = 0; i < 16; i++) {
            int e = tid + i * 256;
            int n = e >> 5, kc = e & 31;
            CPASYNC(sb + SM_B0 + n * 512 + ((kc ^ (n & 7)) << 4), gs + n * 512 + kc * 16);
        }
        CPCOMMIT();
    }
    // cnorm -> smem
    {
        const float4* src = (const float4*)g_cnorm;
        float4* dstv = (float4*)cn_s;
        for (int i = tid; i < 2048; i += 256) dstv[i] = src[i];
    }

    int wm = (wid & 3) * 32, wn = (wid >> 2) * 64;
    int aRow = wm + (lane & 15);
    int aSw = lane & 7;
    int aKo = lane >> 4;
    int bN = wn + (lane & 7) + ((lane >> 4) << 3);
    int bKo = (lane >> 3) & 1;

    for (int t = 0; t < 64; t++) {
        if (t + 1 < 64) {
            const char* gs = (const char*)g_wB + (size_t)(t + 1) * 65536;
            uint32_t bb = sb + (((t + 1) & 1) ? SM_B1 : SM_B0);
#pragma unroll
            for (int i = 0; i < 16; i++) {
                int e = tid + i * 256;
                int n = e >> 5, kc = e & 31;
                CPASYNC(bb + n * 512 + ((kc ^ (n & 7)) << 4), gs + n * 512 + kc * 16);
            }
            CPCOMMIT();
            CPWAIT(1);
        } else {
            CPWAIT(0);
        }
        __syncthreads();

        uint32_t sB = sb + ((t & 1) ? SM_B1 : SM_B0);
        float d[2][8][4];
#pragma unroll
        for (int mi = 0; mi < 2; mi++)
#pragma unroll
            for (int ni = 0; ni < 8; ni++)
#pragma unroll
                for (int u = 0; u < 4; u++) d[mi][ni][u] = 0.f;

#pragma unroll 4
        for (int ks = 0; ks < 16; ks++) {
            int kkA = 2 * ks + aKo;
            uint32_t a0[4], a1[4];
            ldsm4(sb + SM_A + aRow * 512 + ((kkA ^ aSw) << 4), a0[0], a0[1], a0[2], a0[3]);
            ldsm4(sb + SM_A + (aRow + 16) * 512 + ((kkA ^ aSw) << 4), a1[0], a1[1], a1[2], a1[3]);
            int kkB = 2 * ks + bKo;
#pragma unroll
            for (int nb = 0; nb < 4; nb++) {
                int n = bN + nb * 16;
                uint32_t b0, b1, b2, b3;
                ldsm4(sB + n * 512 + ((kkB ^ (lane & 7)) << 4), b0, b1, b2, b3);
                mma16816(d[0][nb * 2], a0, b0, b1);
                mma16816(d[0][nb * 2 + 1], a0, b2, b3);
                mma16816(d[1][nb * 2], a1, b0, b1);
                mma16816(d[1][nb * 2 + 1], a1, b2, b3);
            }
        }

        // epilogue: dist = cn - 2*dot; per-8-col bin min; lanes%4==0 write
#pragma unroll
        for (int mi = 0; mi < 2; mi++) {
#pragma unroll
            for (int ni = 0; ni < 8; ni++) {
                float2 cn2 = *(float2*)&cn_s[t * 128 + wn + ni * 8 + (lane & 3) * 2];
                float v0 = fminf(cn2.x - 2.f * d[mi][ni][0], cn2.y - 2.f * d[mi][ni][1]);
                float v1 = fminf(cn2.x - 2.f * d[mi][ni][2], cn2.y - 2.f * d[mi][ni][3]);
                v0 = fminf(v0, __shfl_xor_sync(0xffffffffu, v0, 1));
                v0 = fminf(v0, __shfl_xor_sync(0xffffffffu, v0, 2));
                v1 = fminf(v1, __shfl_xor_sync(0xffffffffu, v1, 1));
                v1 = fminf(v1, __shfl_xor_sync(0xffffffffu, v1, 2));
                if ((lane & 3) == 0) {
                    int bin = t * 16 + (wn >> 3) + ni;
                    int q0 = qbase + wm + mi * 16 + (lane >> 2);
                    g_bm8[(size_t)bin * NQ + q0] = v0;
                    g_bm8[(size_t)bin * NQ + q0 + 8] = v1;
                }
            }
        }
        __syncthreads();
    }

    // ---- inline exact rescore (bins for this slab are L2-warm) ----
    if (tid < 128) {
        int q = qbase + tid;
        float m = __int_as_float(0x7f800000);
#pragma unroll 8
        for (int i = 0; i < 1024; i++) m = fminf(m, g_bm8[(size_t)i * NQ + q]);
        float thr = m + 2.0f;                    // covers bf16 approx error

        float best = __int_as_float(0x7f800000);
        int bi = 0;
        const float4* zq4 = (const float4*)(g_zT + (size_t)q * DD);
        for (int i = 0; i < 1024; i++) {
            if (g_bm8[(size_t)i * NQ + q] <= thr) {
                float acc[8];
#pragma unroll
                for (int k = 0; k < 8; k++) acc[k] = 0.f;
                const float4* wr = (const float4*)(w + (size_t)i * 8 * DD);
                for (int c4 = 0; c4 < 64; c4++) {
                    float4 zv = __ldg(&zq4[c4]);
#pragma unroll
                    for (int k = 0; k < 8; k++) {
                        float4 wv = __ldg(&wr[k * 64 + c4]);
                        acc[k] = fmaf(zv.x, wv.x, acc[k]);
                        acc[k] = fmaf(zv.y, wv.y, acc[k]);
                        acc[k] = fmaf(zv.z, wv.z, acc[k]);
                        acc[k] = fmaf(zv.w, wv.w, acc[k]);
                    }
                }
#pragma unroll
                for (int k = 0; k < 8; k++) {
                    int c = i * 8 + k;
                    float sc = __ldg(&g_cnorm[c]) - 2.f * acc[k];
                    if (sc < best) { best = sc; bi = c; }
                }
            }
        }
        g_idx[q] = bi;
        out[IDX_OFF + q] = (float)bi;
        atomicAdd(&g_counts[bi], 1);
    }
}

// ---------------- gather + straight-through + loss partials ----------------
__global__ void k_gather(const float* __restrict__ z, const float* __restrict__ w,
                         float* __restrict__ out) {
    int o = blockIdx.x * 256 + threadIdx.x;
    int s = o & 4095;
    int c = (o >> 12) & 255;
    int b = o >> 20;
    int n = b * 4096 + s;
    int id = g_idx[n];
    float zv = z[o];
    float wv = __ldg(w + id * DD + c);
    float d = wv - zv;
    out[o] = zv + d;

    float v = d * d;
#pragma unroll
    for (int off = 16; off; off >>= 1) v += __shfl_xor_sync(0xffffffffu, v, off);
    __shared__ float red[8];
    if ((threadIdx.x & 31) == 0) red[threadIdx.x >> 5] = v;
    __syncthreads();
    if (threadIdx.x == 0) {
        float tsum = 0.f;
#pragma unroll
        for (int i = 0; i < 8; i++) tsum += red[i];
        g_lpart[blockIdx.x] = tsum;
    }
}

__global__ void k_final(float* __restrict__ out) {
    __shared__ double ds[32];
    __shared__ float es[32];
    __shared__ int us[32];
    int t = threadIdx.x, lane = t & 31, warp = t >> 5;

    double lsum = 0.0;
    for (int i = t; i < 16384; i += 1024) lsum += (double)g_lpart[i];

    float ent = 0.f; int uniq = 0;
    for (int c = t; c < NC; c += 1024) {
        int cnt = g_counts[c];
        float p = (float)cnt * (1.0f / 16384.0f);
        ent += p * logf(p + 1e-10f);
        uniq += (cnt > 0);
    }
#pragma unroll
    for (int off = 16; off; off >>= 1) {
        lsum += __shfl_xor_sync(0xffffffffu, lsum, off);
        ent += __shfl_xor_sync(0xffffffffu, ent, off);
        uniq += __shfl_xor_sync(0xffffffffu, uniq, off);
    }
    if (lane == 0) { ds[warp] = lsum; es[warp] = ent; us[warp] = uniq; }
    __syncthreads();
    if (t == 0) {
        double L = 0.0; float E = 0.f; int U = 0;
        for (int i = 0; i < 32; i++) { L += ds[i]; E += es[i]; U += us[i]; }
        out[LOSS_OFF] = 0.25f * (float)(L * (1.0 / 4194304.0));
        out[PERP_OFF] = expf(-E);
        out[UNIQ_OFF] = (float)U;
    }
}

// ---------------- launch ----------------
extern "C" void kernel_launch(void* const* d_in, const int* in_sizes, int n_in,
                              void* d_out, int out_size) {
    const float* z = (const float*)d_in[0];
    const float* w = (const float*)d_in[1];
    float* out = (float*)d_out;

    cudaFuncSetAttribute(k_tc, cudaFuncAttributeMaxDynamicSharedMemorySize, SMEM_SZ);

    k_prepw<<<NC / 8, 256>>>(w);
    k_z<<<dim3(128, 8, 4), dim3(32, 8)>>>(z);
    k_tc<<<128, 256, SMEM_SZ>>>(w, out);
    k_gather<<<ZELEMS / 256, 256>>>(z, w, out);
    k_final<<<1, 1024>>>(out);
}

// round 15
// speedup vs baseline: 2.2421x; 1.5129x over previous
#include <cuda_runtime.h>
#include <cuda_bf16.h>
#include <math.h>
#include <stdint.h>

#define NQ 16384
#define NC 8192
#define DD 256
#define ZELEMS 4194304
#define LOSS_OFF 4194304
#define PERP_OFF 4194305
#define UNIQ_OFF 4194306
#define IDX_OFF  4194307
#define NSM 148

// ---------------- device scratch ----------------
__device__ float          g_cnorm[NC];
__device__ int            g_counts[NC];
__device__ int            g_idx[NQ];
__device__ float          g_lpart[16384];
__device__ int            g_done[128];
__device__ __nv_bfloat16  g_wB[NC * DD];          // bf16 codebook [code][k]
__device__ unsigned char  g_zB[128 * 65536];      // pre-swizzled bf16 A tile per qslab
__device__ float          g_zT[NQ * DD];          // channel-last queries (rescore)
__device__ float          g_bm8[1024 * NQ];       // per-8-code bin minima, bin-major

// ---------------- PTX helpers ----------------
__device__ __forceinline__ uint32_t s2u(const void* p) {
    uint32_t a;
    asm("{ .reg .u64 t; cvta.to.shared.u64 t, %1; cvt.u32.u64 %0, t; }" : "=r"(a) : "l"(p));
    return a;
}
__device__ __forceinline__ void ldsm4(uint32_t addr, uint32_t& r0, uint32_t& r1,
                                      uint32_t& r2, uint32_t& r3) {
    asm volatile("ldmatrix.sync.aligned.m8n8.x4.shared.b16 {%0,%1,%2,%3}, [%4];"
                 : "=r"(r0), "=r"(r1), "=r"(r2), "=r"(r3) : "r"(addr));
}
__device__ __forceinline__ void mma16816(float* d, const uint32_t* a, uint32_t b0, uint32_t b1) {
    asm volatile(
        "mma.sync.aligned.m16n8k16.row.col.f32.bf16.bf16.f32 "
        "{%0,%1,%2,%3},{%4,%5,%6,%7},{%8,%9},{%0,%1,%2,%3};"
        : "+f"(d[0]), "+f"(d[1]), "+f"(d[2]), "+f"(d[3])
        : "r"(a[0]), "r"(a[1]), "r"(a[2]), "r"(a[3]), "r"(b0), "r"(b1));
}
#define CPASYNC(dst, src) \
    asm volatile("cp.async.cg.shared.global [%0], [%1], 16;" :: "r"(dst), "l"(src))
#define CPCOMMIT() asm volatile("cp.async.commit_group;")
#define CPWAIT(n)  asm volatile("cp.async.wait_group %0;" :: "n"(n))

// smem: A 64K | B0 64K | B1 64K | cn 32K
#define SM_A  0
#define SM_B0 65536
#define SM_B1 131072
#define SM_CN 196608
#define SMEM_SZ 229376

// ---------------- fused w-prep: zero counts/done + cnorm + bf16 codebook ------------
__global__ void k_prepw(const float* __restrict__ w) {
    int tid = threadIdx.x;
    if (blockIdx.x < 8) {
        for (int i = tid; i < 1024; i += 256) g_counts[blockIdx.x * 1024 + i] = 0;
    }
    if (blockIdx.x == 8 && tid < 128) g_done[tid] = 0;
    int warp = tid >> 5, lane = tid & 31;
    int c = blockIdx.x * 8 + warp;
    const float* row = w + (size_t)c * DD;
    float s = 0.f;
#pragma unroll
    for (int j = 0; j < 8; j++) {
        float v = row[lane + j * 32];
        s += v * v;
        g_wB[(size_t)c * DD + lane + j * 32] = __float2bfloat16(v);
    }
#pragma unroll
    for (int off = 16; off; off >>= 1) s += __shfl_xor_sync(0xffffffffu, s, off);
    if (lane == 0) g_cnorm[c] = s;
}

// ---------------- fused z-prep: channel-last fp32 + pre-swizzled bf16 A tiles --------
__global__ void k_z(const float* __restrict__ z) {
    __shared__ float tile[32][33];
    int s0 = blockIdx.x * 32, c0 = blockIdx.y * 32, b = blockIdx.z;
    int tx = threadIdx.x, ty = threadIdx.y;
#pragma unroll
    for (int r = 0; r < 4; r++)
        tile[ty + r * 8][tx] = z[b * 1048576 + (c0 + ty + r * 8) * 4096 + s0 + tx];
    __syncthreads();
    int qs = b * 32 + (s0 >> 7);
    unsigned char* zbdst = g_zB + (size_t)qs * 65536;
#pragma unroll
    for (int r = 0; r < 4; r++) {
        int s = s0 + ty + r * 8;
        int c = c0 + tx;
        float v = tile[tx][ty + r * 8];
        g_zT[(size_t)(b * 4096 + s) * DD + c] = v;
        int rr = s & 127;
        int off = rr * 512 + ((((c >> 3) ^ (rr & 7)) << 4)) + (c & 7) * 2;
        *(__nv_bfloat16*)(zbdst + off) = __float2bfloat16(v);
    }
}

// ---------------- persistent HMMA filter + fused exact rescore ----------------
// 8192 jobs = 128 qslabs x 64 ctiles; contiguous strip per CTA; rescore owned slabs.
__global__ void __launch_bounds__(256, 1) k_tc(const float* __restrict__ w,
                                               float* __restrict__ out) {
    extern __shared__ char smem[];
    uint32_t sb = s2u(smem);
    float* cn_s = (float*)(smem + SM_CN);

    int tid = threadIdx.x, lane = tid & 31, wid = tid >> 5;
    int j0 = (int)(((long long)blockIdx.x * 8192) / NSM);
    int j1 = (int)(((long long)(blockIdx.x + 1) * 8192) / NSM);

    // cnorm -> smem
    {
        const float4* src = (const float4*)g_cnorm;
        float4* dstv = (float4*)cn_s;
        for (int i = tid; i < 2048; i += 256) dstv[i] = src[i];
    }

    int wm = (wid & 3) * 32, wn = (wid >> 2) * 64;
    int aRow = wm + (lane & 15);
    int aSw = lane & 7;
    int aKo = lane >> 4;
    int bN = wn + (lane & 7) + ((lane >> 4) << 3);
    int bKo = (lane >> 3) & 1;

    // prefetch B(j0)
    {
        const char* gs = (const char*)g_wB + (size_t)(j0 & 63) * 65536;
#pragma unroll
        for (int i = 0; i < 16; i++) {
            int e = tid + i * 256;
            int n = e >> 5, kc = e & 31;
            CPASYNC(sb + SM_B0 + n * 512 + ((kc ^ (n & 7)) << 4), gs + n * 512 + kc * 16);
        }
        CPCOMMIT();
    }

    int cur_q = -1, buf = 0;
    for (int jj = j0; jj < j1; jj++) {
        int q = jj >> 6, c = jj & 63;
        if (q != cur_q) {                        // A refill (<=2 per strip)
            const char* as = (const char*)g_zB + (size_t)q * 65536;
#pragma unroll
            for (int i = 0; i < 16; i++) {
                int e = tid + i * 256;
                CPASYNC(sb + SM_A + e * 16, as + (size_t)e * 16);
            }
            CPCOMMIT();
            CPWAIT(0);
            __syncthreads();
            cur_q = q;
        }
        if (jj + 1 < j1) {
            const char* gs = (const char*)g_wB + (size_t)((jj + 1) & 63) * 65536;
            uint32_t bb = sb + ((buf ^ 1) ? SM_B1 : SM_B0);
#pragma unroll
            for (int i = 0; i < 16; i++) {
                int e = tid + i * 256;
                int n = e >> 5, kc = e & 31;
                CPASYNC(bb + n * 512 + ((kc ^ (n & 7)) << 4), gs + n * 512 + kc * 16);
            }
            CPCOMMIT();
            CPWAIT(1);
        } else {
            CPWAIT(0);
        }
        __syncthreads();

        uint32_t sB = sb + (buf ? SM_B1 : SM_B0);
        float d[2][8][4];
#pragma unroll
        for (int mi = 0; mi < 2; mi++)
#pragma unroll
            for (int ni = 0; ni < 8; ni++)
#pragma unroll
                for (int u = 0; u < 4; u++) d[mi][ni][u] = 0.f;

#pragma unroll 4
        for (int ks = 0; ks < 16; ks++) {
            int kkA = 2 * ks + aKo;
            uint32_t a0[4], a1[4];
            ldsm4(sb + SM_A + aRow * 512 + ((kkA ^ aSw) << 4), a0[0], a0[1], a0[2], a0[3]);
            ldsm4(sb + SM_A + (aRow + 16) * 512 + ((kkA ^ aSw) << 4), a1[0], a1[1], a1[2], a1[3]);
            int kkB = 2 * ks + bKo;
#pragma unroll
            for (int nb = 0; nb < 4; nb++) {
                int n = bN + nb * 16;
                uint32_t b0, b1, b2, b3;
                ldsm4(sB + n * 512 + ((kkB ^ (lane & 7)) << 4), b0, b1, b2, b3);
                mma16816(d[0][nb * 2], a0, b0, b1);
                mma16816(d[0][nb * 2 + 1], a0, b2, b3);
                mma16816(d[1][nb * 2], a1, b0, b1);
                mma16816(d[1][nb * 2 + 1], a1, b2, b3);
            }
        }

        int qbase = q * 128;
#pragma unroll
        for (int mi = 0; mi < 2; mi++) {
#pragma unroll
            for (int ni = 0; ni < 8; ni++) {
                float2 cn2 = *(float2*)&cn_s[c * 128 + wn + ni * 8 + (lane & 3) * 2];
                float v0 = fminf(cn2.x - 2.f * d[mi][ni][0], cn2.y - 2.f * d[mi][ni][1]);
                float v1 = fminf(cn2.x - 2.f * d[mi][ni][2], cn2.y - 2.f * d[mi][ni][3]);
                v0 = fminf(v0, __shfl_xor_sync(0xffffffffu, v0, 1));
                v0 = fminf(v0, __shfl_xor_sync(0xffffffffu, v0, 2));
                v1 = fminf(v1, __shfl_xor_sync(0xffffffffu, v1, 1));
                v1 = fminf(v1, __shfl_xor_sync(0xffffffffu, v1, 2));
                if ((lane & 3) == 0) {
                    int bin = c * 16 + (wn >> 3) + ni;
                    int q0 = qbase + wm + mi * 16 + (lane >> 2);
                    g_bm8[(size_t)bin * NQ + q0] = v0;
                    g_bm8[(size_t)bin * NQ + q0 + 8] = v1;
                }
            }
        }
        __syncthreads();
        buf ^= 1;
    }

    // ---- publish completion (release) ----
    __syncthreads();
    __threadfence();
    __syncthreads();
    int qf = j0 >> 6, ql = (j1 - 1) >> 6;
    if (tid == 0) {
        for (int q = qf; q <= ql; q++) {
            int lo = max(j0, q * 64), hi = min(j1, q * 64 + 64);
            atomicAdd(&g_done[q], hi - lo);
        }
    }

    // ---- rescore owned qslabs (the one whose last tile is in this strip) ----
    float* sred = (float*)(smem + SM_A);              // reuse A region as scratch
    int*   sidx = (int*)(smem + SM_A + 2048);
    int half = tid >> 7, qloc = tid & 127, bbase = half * 512;

    for (int q = qf; q <= ql; q++) {
        int lastj = q * 64 + 63;
        if (lastj < j0 || lastj >= j1) continue;
        if (tid == 0) {
            while (atomicAdd(&g_done[q], 0) < 64) __nanosleep(64);
        }
        __syncthreads();
        __threadfence();

        int qq = q * 128 + qloc;
        float m = __int_as_float(0x7f800000);
#pragma unroll 8
        for (int i = 0; i < 512; i++)
            m = fminf(m, g_bm8[(size_t)(bbase + i) * NQ + qq]);
        sred[tid] = m;
        __syncthreads();
        float thr = fminf(sred[qloc], sred[qloc + 128]) + 2.0f;   // bf16 error margin

        float best = __int_as_float(0x7f800000);
        int bi = 0;
        const float4* zq4 = (const float4*)(g_zT + (size_t)qq * DD);
        for (int i = 0; i < 512; i++) {
            if (g_bm8[(size_t)(bbase + i) * NQ + qq] <= thr) {
                int bin = bbase + i;
                float acc[8];
#pragma unroll
                for (int k = 0; k < 8; k++) acc[k] = 0.f;
                const float4* wr = (const float4*)(w + (size_t)bin * 8 * DD);
                for (int c4 = 0; c4 < 64; c4++) {
                    float4 zv = __ldg(&zq4[c4]);
#pragma unroll
                    for (int k = 0; k < 8; k++) {
                        float4 wv = __ldg(&wr[k * 64 + c4]);
                        acc[k] = fmaf(zv.x, wv.x, acc[k]);
                        acc[k] = fmaf(zv.y, wv.y, acc[k]);
                        acc[k] = fmaf(zv.z, wv.z, acc[k]);
                        acc[k] = fmaf(zv.w, wv.w, acc[k]);
                    }
                }
#pragma unroll
                for (int k = 0; k < 8; k++) {
                    int c = bin * 8 + k;
                    float sc = cn_s[c] - 2.f * acc[k];
                    if (sc < best) { best = sc; bi = c; }
                }
            }
        }
        __syncthreads();
        sred[tid] = best;
        sidx[tid] = bi;
        __syncthreads();
        if (half == 0) {
            float b2 = sred[tid + 128];
            int i2 = sidx[tid + 128];
            if (b2 < best || (b2 == best && i2 < bi)) { best = b2; bi = i2; }
            g_idx[qq] = bi;
            out[IDX_OFF + qq] = (float)bi;
            atomicAdd(&g_counts[bi], 1);
        }
        __syncthreads();
    }
}

// ---------------- gather + straight-through + loss partials ----------------
__global__ void k_gather(const float* __restrict__ z, const float* __restrict__ w,
                         float* __restrict__ out) {
    int o = blockIdx.x * 256 + threadIdx.x;
    int s = o & 4095;
    int c = (o >> 12) & 255;
    int b = o >> 20;
    int n = b * 4096 + s;
    int id = g_idx[n];
    float zv = z[o];
    float wv = __ldg(w + id * DD + c);
    float d = wv - zv;
    out[o] = zv + d;

    float v = d * d;
#pragma unroll
    for (int off = 16; off; off >>= 1) v += __shfl_xor_sync(0xffffffffu, v, off);
    __shared__ float red[8];
    if ((threadIdx.x & 31) == 0) red[threadIdx.x >> 5] = v;
    __syncthreads();
    if (threadIdx.x == 0) {
        float tsum = 0.f;
#pragma unroll
        for (int i = 0; i < 8; i++) tsum += red[i];
        g_lpart[blockIdx.x] = tsum;
    }
}

__global__ void k_final(float* __restrict__ out) {
    __shared__ double ds[32];
    __shared__ float es[32];
    __shared__ int us[32];
    int t = threadIdx.x, lane = t & 31, warp = t >> 5;

    double lsum = 0.0;
    for (int i = t; i < 16384; i += 1024) lsum += (double)g_lpart[i];

    float ent = 0.f; int uniq = 0;
    for (int c = t; c < NC; c += 1024) {
        int cnt = g_counts[c];
        float p = (float)cnt * (1.0f / 16384.0f);
        ent += p * logf(p + 1e-10f);
        uniq += (cnt > 0);
    }
#pragma unroll
    for (int off = 16; off; off >>= 1) {
        lsum += __shfl_xor_sync(0xffffffffu, lsum, off);
        ent += __shfl_xor_sync(0xffffffffu, ent, off);
        uniq += __shfl_xor_sync(0xffffffffu, uniq, off);
    }
    if (lane == 0) { ds[warp] = lsum; es[warp] = ent; us[warp] = uniq; }
    __syncthreads();
    if (t == 0) {
        double L = 0.0; float E = 0.f; int U = 0;
        for (int i = 0; i < 32; i++) { L += ds[i]; E += es[i]; U += us[i]; }
        out[LOSS_OFF] = 0.25f * (float)(L * (1.0 / 4194304.0));
        out[PERP_OFF] = expf(-E);
        out[UNIQ_OFF] = (float)U;
    }
}

// ---------------- launch ----------------
extern "C" void kernel_launch(void* const* d_in, const int* in_sizes, int n_in,
                              void* d_out, int out_size) {
    const float* z = (const float*)d_in[0];
    const float* w = (const float*)d_in[1];
    float* out = (float*)d_out;

    cudaFuncSetAttribute(k_tc, cudaFuncAttributeMaxDynamicSharedMemorySize, SMEM_SZ);

    k_prepw<<<NC / 8, 256>>>(w);
    k_z<<<dim3(128, 8, 4), dim3(32, 8)>>>(z);
    k_tc<<<NSM, 256, SMEM_SZ>>>(w, out);
    k_gather<<<ZELEMS / 256, 256>>>(z, w, out);
    k_final<<<1, 1024>>>(out);
}